// round 11
// baseline (speedup 1.0000x reference)
#include <cuda_runtime.h>
#include <cuda_bf16.h>
#include <cstdint>

// StatsQuantizer forward, fused single-pass, persistent CTAs.
//   sf[r] = sum(|W[r,:]|)/4096 ;  out = sf*(rint(clamp(W/sf,lo,hi)*8-0.5)+0.5)/8
//
// R6: persistent grid (2 CTAs/SM x 148 SMs = 296), each CTA loops over rows
// with a 1-deep software pipeline: loads for row i+1 issue before row i's
// reduction barrier + store. No wave transitions, no per-CTA load ramp-up
// between rows — the LSU queue stays primed for the whole kernel.

#define ROW_LEN   8192
#define THREADS   512
#define V4_PER_T  4          // 8192 / 4 / 512
#define NUM_CTAS  296        // 2 * 148
#define NUM_ROWS  8192

__device__ __forceinline__ float row_sum_abs(const float4* vv) {
    float s = 0.0f;
#pragma unroll
    for (int i = 0; i < V4_PER_T; ++i)
        s += fabsf(vv[i].x) + fabsf(vv[i].y) + fabsf(vv[i].z) + fabsf(vv[i].w);
    return s;
}

__global__ __launch_bounds__(THREADS, 2)
void statsquant_kernel(const float* __restrict__ w,
                       const float* __restrict__ clip_val,
                       float* __restrict__ out)
{
    const int t = threadIdx.x;
    __shared__ float red[16];
    __shared__ float tot;

    const float hc = 0.5f * clip_val[0];
    const float lo = -hc;
    const float hi = hc - 1e-6f;

    float4 cur[V4_PER_T];
    float4 nxt[V4_PER_T];

    int row = blockIdx.x;
    if (row >= NUM_ROWS) return;

    // prologue: load first row
    {
        const float4* __restrict__ wr =
            reinterpret_cast<const float4*>(w + (size_t)row * ROW_LEN);
#pragma unroll
        for (int i = 0; i < V4_PER_T; ++i)
            cur[i] = __ldcs(&wr[t + i * THREADS]);
    }

    for (; row < NUM_ROWS; row += NUM_CTAS) {
        const int next_row = row + NUM_CTAS;

        // issue next row's loads before this row's barrier/store phase
        if (next_row < NUM_ROWS) {
            const float4* __restrict__ wn =
                reinterpret_cast<const float4*>(w + (size_t)next_row * ROW_LEN);
#pragma unroll
            for (int i = 0; i < V4_PER_T; ++i)
                nxt[i] = __ldcs(&wn[t + i * THREADS]);
        }

        // ---- reduce |cur| across block ----
        float s = row_sum_abs(cur);
#pragma unroll
        for (int o = 16; o > 0; o >>= 1)
            s += __shfl_xor_sync(0xffffffffu, s, o);
        if ((t & 31) == 0) red[t >> 5] = s;
        __syncthreads();
        if (t < 32) {
            float r = (t < 16) ? red[t] : 0.0f;
#pragma unroll
            for (int o = 8; o > 0; o >>= 1)
                r += __shfl_xor_sync(0xffffffffu, r, o);
            if (t == 0) tot = r;
        }
        __syncthreads();

        const float sf     = tot * (1.0f / 4096.0f);
        const float inv_sf = 1.0f / sf;
        const float osc    = sf * 0.125f;

        // ---- quantize + store cur (next-row loads in flight) ----
        float4* __restrict__ orow =
            reinterpret_cast<float4*>(out + (size_t)row * ROW_LEN);
#pragma unroll
        for (int i = 0; i < V4_PER_T; ++i) {
            float4 q;
            float c;
            c = fminf(fmaxf(cur[i].x * inv_sf, lo), hi);
            q.x = (rintf(fmaf(c, 8.0f, -0.5f)) + 0.5f) * osc;
            c = fminf(fmaxf(cur[i].y * inv_sf, lo), hi);
            q.y = (rintf(fmaf(c, 8.0f, -0.5f)) + 0.5f) * osc;
            c = fminf(fmaxf(cur[i].z * inv_sf, lo), hi);
            q.z = (rintf(fmaf(c, 8.0f, -0.5f)) + 0.5f) * osc;
            c = fminf(fmaxf(cur[i].w * inv_sf, lo), hi);
            q.w = (rintf(fmaf(c, 8.0f, -0.5f)) + 0.5f) * osc;
            __stcs(&orow[t + i * THREADS], q);
        }

        // barrier before reusing shared `tot`/`red` + rotate buffers
        __syncthreads();
#pragma unroll
        for (int i = 0; i < V4_PER_T; ++i)
            cur[i] = nxt[i];
    }
}

extern "C" void kernel_launch(void* const* d_in, const int* in_sizes, int n_in,
                              void* d_out, int out_size)
{
    const float* w    = (const float*)d_in[0];
    const float* clip = (const float*)d_in[1];
    float* out        = (float*)d_out;
    (void)in_sizes; (void)n_in; (void)out_size;

    statsquant_kernel<<<NUM_CTAS, THREADS>>>(w, clip, out);
}

// round 13
// speedup vs baseline: 1.0499x; 1.0499x over previous
#include <cuda_runtime.h>
#include <cuda_bf16.h>
#include <cstdint>

// StatsQuantizer forward, fused single-pass.
//   sf[r] = sum(|W[r,:]|)/4096 ;  out = sf*(rint(clamp(W/sf,lo,hi)*8-0.5)+0.5)/8
//
// R11: back to the R2 structure (one short-lived CTA per row, grid=8192,
// work-stealing-balanced) but at the 100%-occupancy point: 1024 threads x
// 2 float4 (8 data regs) -> ~28 regs -> 2 CTAs x 32 warps = 64/64 warps.
// Same single-pass memory pattern (256 MB streaming read + 256 MB streaming
// write), which sits at the mixed-R/W DRAM wall.

#define ROW_LEN   8192
#define THREADS   1024
#define V4_PER_T  2          // 8192 / 4 / 1024

__global__ __launch_bounds__(THREADS, 2)
void statsquant_kernel(const float* __restrict__ w,
                       const float* __restrict__ clip_val,
                       float* __restrict__ out)
{
    const int row = blockIdx.x;
    const size_t base = (size_t)row * ROW_LEN;
    const float4* __restrict__ wrow = reinterpret_cast<const float4*>(w + base);
    float4* __restrict__ orow = reinterpret_cast<float4*>(out + base);

    const int t = threadIdx.x;

    // ---- Load row slice into registers (streaming), accumulate |.| ----
    float4 v[V4_PER_T];
    float s = 0.0f;
#pragma unroll
    for (int i = 0; i < V4_PER_T; ++i) {
        v[i] = __ldcs(&wrow[t + i * THREADS]);
        s += fabsf(v[i].x) + fabsf(v[i].y) + fabsf(v[i].z) + fabsf(v[i].w);
    }

    // ---- Block reduction (32 warps) ----
    __shared__ float red[32];
#pragma unroll
    for (int o = 16; o > 0; o >>= 1)
        s += __shfl_xor_sync(0xffffffffu, s, o);
    if ((t & 31) == 0) red[t >> 5] = s;
    __syncthreads();
    if (t < 32) {
        float r2 = red[t];
#pragma unroll
        for (int o = 16; o > 0; o >>= 1)
            r2 += __shfl_xor_sync(0xffffffffu, r2, o);
        if (t == 0) red[0] = r2;
    }
    __syncthreads();

    const float sf     = red[0] * (1.0f / 4096.0f);
    const float inv_sf = 1.0f / sf;

    const float hc = 0.5f * clip_val[0];
    const float lo = -hc;
    const float hi = hc - 1e-6f;
    const float out_scale = sf * 0.125f;

    // ---- Quantize + streaming store ----
#pragma unroll
    for (int i = 0; i < V4_PER_T; ++i) {
        float4 q;
        float c;
        c = fminf(fmaxf(v[i].x * inv_sf, lo), hi);
        q.x = (rintf(fmaf(c, 8.0f, -0.5f)) + 0.5f) * out_scale;
        c = fminf(fmaxf(v[i].y * inv_sf, lo), hi);
        q.y = (rintf(fmaf(c, 8.0f, -0.5f)) + 0.5f) * out_scale;
        c = fminf(fmaxf(v[i].z * inv_sf, lo), hi);
        q.z = (rintf(fmaf(c, 8.0f, -0.5f)) + 0.5f) * out_scale;
        c = fminf(fmaxf(v[i].w * inv_sf, lo), hi);
        q.w = (rintf(fmaf(c, 8.0f, -0.5f)) + 0.5f) * out_scale;
        __stcs(&orow[t + i * THREADS], q);
    }
}

extern "C" void kernel_launch(void* const* d_in, const int* in_sizes, int n_in,
                              void* d_out, int out_size)
{
    const float* w    = (const float*)d_in[0];
    const float* clip = (const float*)d_in[1];
    float* out        = (float*)d_out;
    (void)in_sizes; (void)n_in; (void)out_size;

    statsquant_kernel<<<ROW_LEN, THREADS>>>(w, clip, out);
}

// round 14
// speedup vs baseline: 1.1326x; 1.0788x over previous
#include <cuda_runtime.h>
#include <cuda_bf16.h>
#include <cstdint>

// StatsQuantizer forward, fused single-pass.
//   sf[r] = sum(|W[r,:]|)/4096 ;  out = sf*(rint(clamp(W/sf,lo,hi)*8-0.5)+0.5)/8
//
// R13: R2 shape (best measured: 512 thr x 4 float4, one CTA per row,
// grid=8192) with critical-path trims only:
//  - single-__syncthreads reduction (all threads sum the 16 warp partials
//    from smem themselves; broadcast reads, no second barrier)
//  - __ldcg loads (L2-only; no L1 allocate for zero-reuse data)
//  - __stcs streaming stores
// Memory pattern unchanged: 256 MB streaming read + 256 MB streaming write,
// at the mixed-R/W HBM wall.

#define ROW_LEN   8192
#define THREADS   512
#define V4_PER_T  4          // 8192 / 4 / 512
#define NWARPS    (THREADS / 32)

__global__ __launch_bounds__(THREADS, 3)
void statsquant_kernel(const float* __restrict__ w,
                       const float* __restrict__ clip_val,
                       float* __restrict__ out)
{
    const int row = blockIdx.x;
    const size_t base = (size_t)row * ROW_LEN;
    const float4* __restrict__ wrow = reinterpret_cast<const float4*>(w + base);
    float4* __restrict__ orow = reinterpret_cast<float4*>(out + base);

    const int t = threadIdx.x;

    // ---- Load row slice into registers (L2-only), accumulate |.| ----
    float4 v[V4_PER_T];
    float s = 0.0f;
#pragma unroll
    for (int i = 0; i < V4_PER_T; ++i) {
        v[i] = __ldcg(&wrow[t + i * THREADS]);
        s += fabsf(v[i].x) + fabsf(v[i].y) + fabsf(v[i].z) + fabsf(v[i].w);
    }

    // ---- Reduction: warp reduce, one barrier, every thread sums partials ----
    __shared__ float red[NWARPS];
#pragma unroll
    for (int o = 16; o > 0; o >>= 1)
        s += __shfl_xor_sync(0xffffffffu, s, o);
    if ((t & 31) == 0) red[t >> 5] = s;
    __syncthreads();

    float tot = 0.0f;
#pragma unroll
    for (int i = 0; i < NWARPS; ++i)
        tot += red[i];                    // broadcast LDS, conflict-free

    const float sf     = tot * (1.0f / 4096.0f);
    const float inv_sf = 1.0f / sf;

    const float hc = 0.5f * clip_val[0];
    const float lo = -hc;
    const float hi = hc - 1e-6f;
    const float out_scale = sf * 0.125f;

    // ---- Quantize + streaming store ----
#pragma unroll
    for (int i = 0; i < V4_PER_T; ++i) {
        float4 q;
        float c;
        c = fminf(fmaxf(v[i].x * inv_sf, lo), hi);
        q.x = (rintf(fmaf(c, 8.0f, -0.5f)) + 0.5f) * out_scale;
        c = fminf(fmaxf(v[i].y * inv_sf, lo), hi);
        q.y = (rintf(fmaf(c, 8.0f, -0.5f)) + 0.5f) * out_scale;
        c = fminf(fmaxf(v[i].z * inv_sf, lo), hi);
        q.z = (rintf(fmaf(c, 8.0f, -0.5f)) + 0.5f) * out_scale;
        c = fminf(fmaxf(v[i].w * inv_sf, lo), hi);
        q.w = (rintf(fmaf(c, 8.0f, -0.5f)) + 0.5f) * out_scale;
        __stcs(&orow[t + i * THREADS], q);
    }
}

extern "C" void kernel_launch(void* const* d_in, const int* in_sizes, int n_in,
                              void* d_out, int out_size)
{
    const float* w    = (const float*)d_in[0];
    const float* clip = (const float*)d_in[1];
    float* out        = (float*)d_out;
    (void)in_sizes; (void)n_in; (void)out_size;

    statsquant_kernel<<<ROW_LEN, THREADS>>>(w, clip, out);
}